// round 13
// baseline (speedup 1.0000x reference)
#include <cuda_runtime.h>
#include <cuda_fp16.h>
#include <cstdint>
#include <cstddef>

// Problem constants
#define BB 512
#define TT 128
#define HH 1024
#define BH (512*1024)

// ---------------- device scratch (no allocations allowed) ----------------
__device__ __align__(16) __half g_U1[1088 * 4096];  // [k][n] row-major, gate-interleaved n
__device__ __align__(16) __half g_U2[2048 * 4096];
__device__ __align__(16) float  g_bp1[4096];
__device__ __align__(16) float  g_bp2[4096];
__device__ __align__(16) __half g_xh[BB * TT * 64];
__device__ __align__(16) __half g_h1[2][BH];
__device__ __align__(16) __half g_h2[2][BH];
__device__ __align__(16) float  g_c1[BH];
__device__ __align__(16) float  g_c2[BH];

// ---------------- ptx helpers ----------------
__device__ __forceinline__ void cp16(uint32_t dst, const void* src) {
    asm volatile("cp.async.cg.shared.global [%0], [%1], 16;\n" :: "r"(dst), "l"(src));
}
__device__ __forceinline__ void cp_commit() { asm volatile("cp.async.commit_group;\n"); }
template<int N> __device__ __forceinline__ void cp_wait() {
    asm volatile("cp.async.wait_group %0;\n" :: "n"(N));
}
__device__ __forceinline__ void ldmA(uint32_t* r, uint32_t a) {
    asm volatile("ldmatrix.sync.aligned.m8n8.x4.shared.b16 {%0,%1,%2,%3}, [%4];\n"
        : "=r"(r[0]), "=r"(r[1]), "=r"(r[2]), "=r"(r[3]) : "r"(a));
}
__device__ __forceinline__ void ldmBT(uint32_t* r, uint32_t a) {
    asm volatile("ldmatrix.sync.aligned.m8n8.x4.trans.shared.b16 {%0,%1,%2,%3}, [%4];\n"
        : "=r"(r[0]), "=r"(r[1]), "=r"(r[2]), "=r"(r[3]) : "r"(a));
}
__device__ __forceinline__ void mma_f16(float c[4], const uint32_t a[4], uint32_t b0, uint32_t b1) {
    asm volatile("mma.sync.aligned.m16n8k16.row.col.f32.f16.f16.f32 "
        "{%0,%1,%2,%3}, {%4,%5,%6,%7}, {%8,%9}, {%0,%1,%2,%3};\n"
        : "+f"(c[0]), "+f"(c[1]), "+f"(c[2]), "+f"(c[3])
        : "r"(a[0]), "r"(a[1]), "r"(a[2]), "r"(a[3]), "r"(b0), "r"(b1));
}
__device__ __forceinline__ float tanh_ap(float x) {
    float y; asm("tanh.approx.f32 %0, %1;" : "=f"(y) : "f"(x)); return y;
}
__device__ __forceinline__ float sigm_t(float x) {   // sigmoid via 1 MUFU
    return fmaf(tanh_ap(0.5f * x), 0.5f, 0.5f);
}

// ---------------- pack / prep kernels (run each replay; coalesced) ----------------
__global__ void pack_u1(const float* __restrict__ W1, const float* __restrict__ U1) {
    int idx = blockIdx.x * 256 + threadIdx.x;      // 1088*1024 threads
    if (idx >= 1088 * 1024) return;
    int j = idx & 1023, k = idx >> 10;
    const float* src = (k < 64) ? (W1 + (size_t)k * 4096)
                                : (U1 + (size_t)(k - 64) * 4096);
    union { __half h[4]; uint2 u; } o;
    o.h[0] = __float2half(src[j]);
    o.h[1] = __float2half(src[1024 + j]);
    o.h[2] = __float2half(src[2048 + j]);
    o.h[3] = __float2half(src[3072 + j]);
    *(uint2*)(g_U1 + (size_t)k * 4096 + 4 * j) = o.u;
}
__global__ void pack_u2(const float* __restrict__ W2, const float* __restrict__ U2) {
    int idx = blockIdx.x * 256 + threadIdx.x;      // 2048*1024 threads
    if (idx >= 2048 * 1024) return;
    int j = idx & 1023, k = idx >> 10;
    const float* src = (k < 1024) ? (W2 + (size_t)k * 4096)
                                  : (U2 + (size_t)(k - 1024) * 4096);
    union { __half h[4]; uint2 u; } o;
    o.h[0] = __float2half(src[j]);
    o.h[1] = __float2half(src[1024 + j]);
    o.h[2] = __float2half(src[2048 + j]);
    o.h[3] = __float2half(src[3072 + j]);
    *(uint2*)(g_U2 + (size_t)k * 4096 + 4 * j) = o.u;
}
__global__ void prep_misc(const float* __restrict__ x,
                          const float* __restrict__ b1, const float* __restrict__ b2) {
    int i = blockIdx.x * 256 + threadIdx.x;
    if (i < BB * TT * 64) g_xh[i] = __float2half(x[i]);
    if (i < BH) {
        g_c1[i] = 0.f; g_c2[i] = 0.f;
        __half z = __float2half(0.f);
        g_h1[0][i] = z; g_h1[1][i] = z; g_h2[0][i] = z; g_h2[1][i] = z;
    }
    if (i < 4096) {
        int j = i >> 2, g = i & 3;
        g_bp1[i] = b1[g * 1024 + j];
        g_bp2[i] = b2[g * 1024 + j];
    }
}

// ---------------- paired fused LSTM step (R8 body + PDL overlap) ----------------
// bids 0-127 -> HEAVY layer1 tiles (K=2048); bids 128-255 -> LIGHT layer0 (K=1088).
// PDL: this launch prelaunches while the previous drains. Weights (B tiles) are
// step-invariant -> prefetch 3 stages of B BEFORE cudaGridDependencySynchronize();
// all h/c-state reads (A tiles, epilogue) happen after it. First global write is
// after the sync, so the h1 WAR hazard cannot fire. Group order gB,gA01,gA2 keeps
// the R8 cp_wait<1> invariant.
#define A_PITCH 72              // halves (64 + 8 pad)
#define B_PITCH 136             // halves (128 + 8 pad)
#define STAGE_A (128 * A_PITCH * 2)     // 18432
#define STAGE_B (64 * B_PITCH * 2)      // 17408
#define STAGE   (STAGE_A + STAGE_B)     // 35840
#define SMEM_TOTAL (3 * STAGE)          // 107520

__global__ __launch_bounds__(256, 2) void lstm_pair(int t0, int t1) {
    const int bid = blockIdx.x;
    const int layer = (bid < 128) ? 1 : 0;        // heavy tiles on low bids
    const int tile = bid & 127;
    const int t = layer ? t1 : t0;
    if (t < 0 || t > 127) return;

    extern __shared__ __align__(16) char smem[];
    const int tid = threadIdx.x;
    const int wid = tid >> 5, lane = tid & 31;
    const int mblk = (tile >> 5) << 7;
    const int nblk = (tile & 31) << 7;

    const int cur = t & 1, prev = cur ^ 1;
    const __half *A0, *A1, *Bw; const float* biasp; float* cst; __half* hout;
    int lda0, K0, KTOT;
    if (layer == 0) {
        A0 = g_xh + t * 64; lda0 = TT * 64; K0 = 64;
        A1 = g_h1[prev]; Bw = g_U1; biasp = g_bp1; cst = g_c1; hout = g_h1[cur]; KTOT = 1088;
    } else {
        A0 = g_h1[cur]; lda0 = 1024; K0 = 1024;
        A1 = g_h2[prev]; Bw = g_U2; biasp = g_bp2; cst = g_c2; hout = g_h2[cur]; KTOT = 2048;
    }
    const int KT = KTOT >> 6;

    const uint32_t sSm = (uint32_t)__cvta_generic_to_shared(smem);
    const int wm = (wid >> 1) * 32;     // 4 m-warps x 32 rows
    const int wn = (wid & 1) * 64;      // 2 n-warps x 64 cols

    float acc[2][8][4];
#pragma unroll
    for (int a = 0; a < 2; a++)
#pragma unroll
        for (int b = 0; b < 8; b++)
#pragma unroll
            for (int c = 0; c < 4; c++) acc[a][b][c] = 0.f;

    // B (weights, step-invariant — safe before griddepsync)
    auto issueB = [&](int kt) {
        const int st = kt % 3;
        const int kg = kt << 6;
        const uint32_t bBase = sSm + st * STAGE + STAGE_A;
#pragma unroll
        for (int jj = 0; jj < 4; jj++) {
            int item = jj * 256 + tid;
            int row = item >> 4, c16 = item & 15;
            cp16(bBase + (uint32_t)(row * (B_PITCH * 2) + c16 * 16),
                 Bw + (size_t)(kg + row) * 4096 + nblk + c16 * 8);
        }
    };
    // A (h/x state — only after griddepsync)
    auto issueA = [&](int kt) {
        const int st = kt % 3;
        const int kg = kt << 6;
        const __half* srcA; int lda, kr;
        if (kg < K0) { srcA = A0; lda = lda0; kr = kg; }
        else         { srcA = A1; lda = 1024; kr = kg - K0; }
        const uint32_t aBase = sSm + st * STAGE;
#pragma unroll
        for (int jj = 0; jj < 4; jj++) {
            int item = jj * 256 + tid;
            int row = item >> 3, c8 = item & 7;
            cp16(aBase + (uint32_t)(row * (A_PITCH * 2) + c8 * 16),
                 srcA + (size_t)(mblk + row) * lda + kr + c8 * 8);
        }
    };
    auto issue = [&](int kt) { issueA(kt); issueB(kt); cp_commit(); };

    const uint32_t aLane = (uint32_t)(((wm + (lane & 15)) * A_PITCH + ((lane >> 4) << 3)) * 2);
    const uint32_t bLane = (uint32_t)(((lane & 15) * B_PITCH + wn + ((lane >> 4) << 3)) * 2);

    uint32_t af[2][2][4], bf[2][4][4];
    auto load_frags = [&](uint32_t aB, uint32_t bB, int kk, int buf) {
#pragma unroll
        for (int mi = 0; mi < 2; mi++)
            ldmA(af[buf][mi], aB + aLane + (uint32_t)((mi * 16 * A_PITCH + kk * 16) * 2));
#pragma unroll
        for (int nj = 0; nj < 4; nj++)
            ldmBT(bf[buf][nj], bB + bLane + (uint32_t)((kk * 16 * B_PITCH + nj * 16) * 2));
    };
    auto do_mma = [&](int buf) {
#pragma unroll
        for (int mi = 0; mi < 2; mi++)
#pragma unroll
            for (int ni = 0; ni < 8; ni++)
                mma_f16(acc[mi][ni], af[buf][mi],
                        bf[buf][ni >> 1][(ni & 1) * 2], bf[buf][ni >> 1][(ni & 1) * 2 + 1]);
    };

    // ---- PDL prologue ----
    // Prefetch all 3 stages of weights while the previous grid is still running.
    issueB(0); issueB(1); issueB(2); cp_commit();   // group gB
#if __CUDA_ARCH__ >= 900
    cudaGridDependencySynchronize();                // previous grid fully done
    cudaTriggerProgrammaticLaunchCompletion();      // let the next launch prelaunch
#endif
    issueA(0); issueA(1); cp_commit();              // group gA01
    issueA(2); cp_commit();                         // group gA2
    cp_wait<1>();                                   // gB + gA01 done -> stages 0,1 ready
    __syncthreads();
    load_frags(sSm, sSm + STAGE_A, 0, 0);

    for (int kt = 0; kt < KT; kt++) {
        const uint32_t aB = sSm + (kt % 3) * STAGE;
        const uint32_t bB = aB + STAGE_A;
        // kk = 0..2: load next frags (dual buffer) then MMA current
#pragma unroll
        for (int kk = 0; kk < 3; kk++) {
            load_frags(aB, bB, kk + 1, (kk & 1) ^ 1);
            do_mma(kk & 1);
        }
        // publish stage kt+1 CTA-wide + license rewrite of stage kt
        if (kt + 1 < KT) cp_wait<1>(); else cp_wait<0>();
        __syncthreads();
        // kk = 3: prefetch next chunk's kk0 frags + refill smem, both in MMA shadow
        if (kt + 1 < KT) {
            const uint32_t aB2 = sSm + ((kt + 1) % 3) * STAGE;
            load_frags(aB2, aB2 + STAGE_A, 0, 0);
        }
        if (kt + 3 < KT) issue(kt + 3);
        do_mma(1);
    }

    // -------- epilogue: smem patch -> gates -> c,h (coalesced, MUFU-light) --------
    __syncthreads();                       // everyone done with stage smem
    float* patch = (float*)smem;           // [128][136] floats
#pragma unroll
    for (int mi = 0; mi < 2; mi++)
#pragma unroll
        for (int ni = 0; ni < 8; ni++) {
            int r = wm + mi * 16 + (lane >> 2);
            int c = wn + ni * 8 + (lane & 3) * 2;
            *(float2*)(patch + r * B_PITCH + c)       = make_float2(acc[mi][ni][0], acc[mi][ni][1]);
            *(float2*)(patch + (r + 8) * B_PITCH + c) = make_float2(acc[mi][ni][2], acc[mi][ni][3]);
        }
    __syncthreads();

    const int jbase = nblk >> 2;           // 32 hidden units per CTA n-tile
#pragma unroll 4
    for (int it = 0; it < 16; it++) {
        int idx = it * 256 + tid;
        int row = idx >> 5;
        int u = idx & 31;
        float4 z = *(float4*)(patch + row * B_PITCH + u * 4);
        float4 bb = *(const float4*)(biasp + ((jbase + u) << 2));
        float ig = sigm_t(z.x + bb.x);
        float fg = sigm_t(z.y + bb.y);
        float gg = tanh_ap(z.z + bb.z);
        float og = sigm_t(z.w + bb.w);
        size_t off = (size_t)(mblk + row) * 1024 + jbase + u;
        float cn = fg * cst[off] + ig * gg;
        cst[off] = cn;
        hout[off] = __float2half(og * tanh_ap(cn));
    }
}

// ---------------- dense sigmoid head ----------------
__global__ void head_kernel(const float* __restrict__ Wd, const float* __restrict__ bd,
                            float* __restrict__ out) {
    int b = blockIdx.x;
    const __half* h = g_h2[1] + (size_t)b * 1024;   // t=127 -> cur buffer = 1
    float s = 0.f;
    for (int j = threadIdx.x; j < 1024; j += 128)
        s += __half2float(h[j]) * Wd[j];
#pragma unroll
    for (int o = 16; o; o >>= 1) s += __shfl_xor_sync(0xffffffffu, s, o);
    __shared__ float ws[4];
    if ((threadIdx.x & 31) == 0) ws[threadIdx.x >> 5] = s;
    __syncthreads();
    if (threadIdx.x == 0) {
        float t = ws[0] + ws[1] + ws[2] + ws[3] + bd[0];
        out[b] = 1.f / (1.f + __expf(-t));
    }
}

// ---------------- launch ----------------
extern "C" void kernel_launch(void* const* d_in, const int* in_sizes, int n_in,
                              void* d_out, int out_size) {
    (void)in_sizes; (void)n_in; (void)out_size;
    const float* x  = (const float*)d_in[0];
    const float* W1 = (const float*)d_in[1];
    const float* U1 = (const float*)d_in[2];
    const float* b1 = (const float*)d_in[3];
    const float* W2 = (const float*)d_in[4];
    const float* U2 = (const float*)d_in[5];
    const float* b2 = (const float*)d_in[6];
    const float* Wd = (const float*)d_in[7];
    const float* bd = (const float*)d_in[8];
    float* out = (float*)d_out;

    cudaFuncSetAttribute(lstm_pair, cudaFuncAttributeMaxDynamicSharedMemorySize, SMEM_TOTAL);

    pack_u1<<<(1088 * 1024 + 255) / 256, 256>>>(W1, U1);       // 1
    pack_u2<<<(2048 * 1024 + 255) / 256, 256>>>(W2, U2);       // 2
    prep_misc<<<(BB * TT * 64 + 255) / 256, 256>>>(x, b1, b2); // 3

    // PDL-attributed wavefront launches: each prelaunches under the previous one
    cudaLaunchAttribute attr[1];
    attr[0].id = cudaLaunchAttributeProgrammaticStreamSerialization;
    attr[0].val.programmaticStreamSerializationAllowed = 1;

    for (int t0 = 0; t0 <= 128; t0++) {                        // 4 = first lstm (ncu slot)
        cudaLaunchConfig_t cfg = {};
        cfg.gridDim = dim3((t0 == 128) ? 128 : 256, 1, 1);     // last step: heavy-only
        cfg.blockDim = dim3(256, 1, 1);
        cfg.dynamicSmemBytes = SMEM_TOTAL;
        cfg.stream = 0;
        cfg.attrs = attr;
        cfg.numAttrs = 1;
        cudaLaunchKernelEx(&cfg, lstm_pair, t0, t0 - 1);
    }
    head_kernel<<<512, 128>>>(Wd, bd, out);                    // serialized (no PDL)
}

// round 14
// speedup vs baseline: 1.0710x; 1.0710x over previous
#include <cuda_runtime.h>
#include <cuda_fp16.h>
#include <cstdint>
#include <cstddef>

// Problem constants
#define BB 512
#define TT 128
#define HH 1024
#define BH (512*1024)

// ---------------- device scratch (no allocations allowed) ----------------
__device__ __align__(16) __half g_U1[1088 * 4096];  // [k][n] row-major, gate-interleaved n
__device__ __align__(16) __half g_U2[2048 * 4096];
__device__ __align__(16) float  g_bp1[4096];
__device__ __align__(16) float  g_bp2[4096];
__device__ __align__(16) __half g_xh[BB * TT * 64];
__device__ __align__(16) __half g_h1[2][BH];
__device__ __align__(16) __half g_h2[2][BH];
__device__ __align__(16) float  g_c1[BH];
__device__ __align__(16) float  g_c2[BH];
__device__ __align__(16) float  g_zp[128 * 16384];  // split-K partials (8MB)
__device__ int g_zflag[128];                        // monotonic step tokens (init -1)

// ---------------- ptx helpers ----------------
__device__ __forceinline__ void cp16(uint32_t dst, const void* src) {
    asm volatile("cp.async.cg.shared.global [%0], [%1], 16;\n" :: "r"(dst), "l"(src));
}
__device__ __forceinline__ void cp_commit() { asm volatile("cp.async.commit_group;\n"); }
template<int N> __device__ __forceinline__ void cp_wait() {
    asm volatile("cp.async.wait_group %0;\n" :: "n"(N));
}
__device__ __forceinline__ void ldmA(uint32_t* r, uint32_t a) {
    asm volatile("ldmatrix.sync.aligned.m8n8.x4.shared.b16 {%0,%1,%2,%3}, [%4];\n"
        : "=r"(r[0]), "=r"(r[1]), "=r"(r[2]), "=r"(r[3]) : "r"(a));
}
__device__ __forceinline__ void ldmBT(uint32_t* r, uint32_t a) {
    asm volatile("ldmatrix.sync.aligned.m8n8.x4.trans.shared.b16 {%0,%1,%2,%3}, [%4];\n"
        : "=r"(r[0]), "=r"(r[1]), "=r"(r[2]), "=r"(r[3]) : "r"(a));
}
__device__ __forceinline__ void mma_f16(float c[4], const uint32_t a[4], uint32_t b0, uint32_t b1) {
    asm volatile("mma.sync.aligned.m16n8k16.row.col.f32.f16.f16.f32 "
        "{%0,%1,%2,%3}, {%4,%5,%6,%7}, {%8,%9}, {%0,%1,%2,%3};\n"
        : "+f"(c[0]), "+f"(c[1]), "+f"(c[2]), "+f"(c[3])
        : "r"(a[0]), "r"(a[1]), "r"(a[2]), "r"(a[3]), "r"(b0), "r"(b1));
}
__device__ __forceinline__ float tanh_ap(float x) {
    float y; asm("tanh.approx.f32 %0, %1;" : "=f"(y) : "f"(x)); return y;
}
__device__ __forceinline__ float sigm_t(float x) {   // sigmoid via 1 MUFU
    return fmaf(tanh_ap(0.5f * x), 0.5f, 0.5f);
}
__device__ __forceinline__ int ld_acq(const int* p) {
    int v;
    asm volatile("ld.global.acquire.gpu.b32 %0, [%1];" : "=r"(v) : "l"(p) : "memory");
    return v;
}

// ---------------- pack / prep kernels (run each replay; coalesced) ----------------
__global__ void pack_u1(const float* __restrict__ W1, const float* __restrict__ U1) {
    int idx = blockIdx.x * 256 + threadIdx.x;      // 1088*1024 threads
    if (idx >= 1088 * 1024) return;
    int j = idx & 1023, k = idx >> 10;
    const float* src = (k < 64) ? (W1 + (size_t)k * 4096)
                                : (U1 + (size_t)(k - 64) * 4096);
    union { __half h[4]; uint2 u; } o;
    o.h[0] = __float2half(src[j]);
    o.h[1] = __float2half(src[1024 + j]);
    o.h[2] = __float2half(src[2048 + j]);
    o.h[3] = __float2half(src[3072 + j]);
    *(uint2*)(g_U1 + (size_t)k * 4096 + 4 * j) = o.u;
}
__global__ void pack_u2(const float* __restrict__ W2, const float* __restrict__ U2) {
    int idx = blockIdx.x * 256 + threadIdx.x;      // 2048*1024 threads
    if (idx >= 2048 * 1024) return;
    int j = idx & 1023, k = idx >> 10;
    const float* src = (k < 1024) ? (W2 + (size_t)k * 4096)
                                  : (U2 + (size_t)(k - 1024) * 4096);
    union { __half h[4]; uint2 u; } o;
    o.h[0] = __float2half(src[j]);
    o.h[1] = __float2half(src[1024 + j]);
    o.h[2] = __float2half(src[2048 + j]);
    o.h[3] = __float2half(src[3072 + j]);
    *(uint2*)(g_U2 + (size_t)k * 4096 + 4 * j) = o.u;
}
__global__ void prep_misc(const float* __restrict__ x,
                          const float* __restrict__ b1, const float* __restrict__ b2) {
    int i = blockIdx.x * 256 + threadIdx.x;
    if (i < BB * TT * 64) g_xh[i] = __float2half(x[i]);
    if (i < BH) {
        g_c1[i] = 0.f; g_c2[i] = 0.f;
        __half z = __float2half(0.f);
        g_h1[0][i] = z; g_h1[1][i] = z; g_h2[0][i] = z; g_h2[1][i] = z;
    }
    if (i < 4096) {
        int j = i >> 2, g = i & 3;
        g_bp1[i] = b1[g * 1024 + j];
        g_bp2[i] = b2[g * 1024 + j];
    }
    if (i < 128) g_zflag[i] = -1;
}

// ---------------- GEMM tile body (single code copy; R12 pipeline) ----------------
// mode 0 = normal epilogue; 1 = write split-K partial + flag; 2 = spin+combine+epilogue
#define A_PITCH 72              // halves (64 + 8 pad)
#define B_PITCH 136             // halves (128 + 8 pad)
#define STAGE_A (128 * A_PITCH * 2)     // 18432
#define STAGE_B (64 * B_PITCH * 2)      // 17408
#define STAGE   (STAGE_A + STAGE_B)     // 35840
#define SMEM_TOTAL (3 * STAGE)          // 107520

__device__ __noinline__ void gemm_tile(int layer, int t, int tile,
                                       int kbeg, int kend, int mode, char* smem) {
    const int tid = threadIdx.x;
    const int wid = tid >> 5, lane = tid & 31;
    const int mblk = (tile >> 5) << 7;
    const int nblk = (tile & 31) << 7;

    const int cur = t & 1, prev = cur ^ 1;
    const __half *A0, *A1, *Bw; const float* biasp; float* cst; __half* hout;
    int lda0, K0;
    if (layer == 0) {
        A0 = g_xh + t * 64; lda0 = TT * 64; K0 = 64;
        A1 = g_h1[prev]; Bw = g_U1; biasp = g_bp1; cst = g_c1; hout = g_h1[cur];
    } else {
        A0 = g_h1[cur]; lda0 = 1024; K0 = 1024;
        A1 = g_h2[prev]; Bw = g_U2; biasp = g_bp2; cst = g_c2; hout = g_h2[cur];
    }

    const uint32_t sSm = (uint32_t)__cvta_generic_to_shared(smem);
    const int wm = (wid >> 1) * 32;     // 4 m-warps x 32 rows
    const int wn = (wid & 1) * 64;      // 2 n-warps x 64 cols

    __syncthreads();                    // smem safe vs prior phase of this CTA

    float acc[2][8][4];
#pragma unroll
    for (int a = 0; a < 2; a++)
#pragma unroll
        for (int b = 0; b < 8; b++)
#pragma unroll
            for (int c = 0; c < 4; c++) acc[a][b][c] = 0.f;

    auto issue = [&](int kt) {
        const int st = kt % 3;
        const int kg = kt << 6;
        const __half* srcA; int lda, kr;
        if (kg < K0) { srcA = A0; lda = lda0; kr = kg; }
        else         { srcA = A1; lda = 1024; kr = kg - K0; }
        const uint32_t aBase = sSm + st * STAGE;
#pragma unroll
        for (int jj = 0; jj < 4; jj++) {
            int item = jj * 256 + tid;
            int row = item >> 3, c8 = item & 7;
            cp16(aBase + (uint32_t)(row * (A_PITCH * 2) + c8 * 16),
                 srcA + (size_t)(mblk + row) * lda + kr + c8 * 8);
        }
        const uint32_t bBase = aBase + STAGE_A;
#pragma unroll
        for (int jj = 0; jj < 4; jj++) {
            int item = jj * 256 + tid;
            int row = item >> 4, c16 = item & 15;
            cp16(bBase + (uint32_t)(row * (B_PITCH * 2) + c16 * 16),
                 Bw + (size_t)(kg + row) * 4096 + nblk + c16 * 8);
        }
        cp_commit();
    };

    const uint32_t aLane = (uint32_t)(((wm + (lane & 15)) * A_PITCH + ((lane >> 4) << 3)) * 2);
    const uint32_t bLane = (uint32_t)(((lane & 15) * B_PITCH + wn + ((lane >> 4) << 3)) * 2);

    uint32_t af[2][2][4], bf[2][4][4];
    auto load_frags = [&](uint32_t aB, uint32_t bB, int kk, int buf) {
#pragma unroll
        for (int mi = 0; mi < 2; mi++)
            ldmA(af[buf][mi], aB + aLane + (uint32_t)((mi * 16 * A_PITCH + kk * 16) * 2));
#pragma unroll
        for (int nj = 0; nj < 4; nj++)
            ldmBT(bf[buf][nj], bB + bLane + (uint32_t)((kk * 16 * B_PITCH + nj * 16) * 2));
    };
    auto do_mma = [&](int buf) {
#pragma unroll
        for (int mi = 0; mi < 2; mi++)
#pragma unroll
            for (int ni = 0; ni < 8; ni++)
                mma_f16(acc[mi][ni], af[buf][mi],
                        bf[buf][ni >> 1][(ni & 1) * 2], bf[buf][ni >> 1][(ni & 1) * 2 + 1]);
    };

    // prologue (all call sites have kend-kbeg >= 8)
    issue(kbeg); issue(kbeg + 1);
    cp_wait<1>();
    __syncthreads();
    {
        const uint32_t aB0 = sSm + (kbeg % 3) * STAGE;
        load_frags(aB0, aB0 + STAGE_A, 0, 0);
    }
    issue(kbeg + 2);

    for (int kt = kbeg; kt < kend; kt++) {
        const uint32_t aB = sSm + (kt % 3) * STAGE;
        const uint32_t bB = aB + STAGE_A;
#pragma unroll
        for (int kk = 0; kk < 3; kk++) {
            load_frags(aB, bB, kk + 1, (kk & 1) ^ 1);
            do_mma(kk & 1);
        }
        if (kt + 1 < kend) cp_wait<1>(); else cp_wait<0>();
        __syncthreads();
        if (kt + 1 < kend) {
            const uint32_t aB2 = sSm + ((kt + 1) % 3) * STAGE;
            load_frags(aB2, aB2 + STAGE_A, 0, 0);
        }
        if (kt + 3 < kend) issue(kt + 3);
        do_mma(1);
    }

    if (mode == 1) {
        // -------- split-K partial: write raw z to scratch + release flag --------
        float* zp = g_zp + (size_t)tile * 16384;
#pragma unroll
        for (int mi = 0; mi < 2; mi++)
#pragma unroll
            for (int ni = 0; ni < 8; ni++) {
                int r = wm + mi * 16 + (lane >> 2);
                int c = wn + ni * 8 + (lane & 3) * 2;
                *(float2*)(zp + r * 128 + c)       = make_float2(acc[mi][ni][0], acc[mi][ni][1]);
                *(float2*)(zp + (r + 8) * 128 + c) = make_float2(acc[mi][ni][2], acc[mi][ni][3]);
            }
        __threadfence();
        __syncthreads();
        if (tid == 0) atomicExch(&g_zflag[tile], t);
        return;
    }

    if (mode == 2) {
        // -------- combine: wait for the partial, add into acc --------
        const float* zp = g_zp + (size_t)tile * 16384;
        if (tid == 0) {
            while (ld_acq(&g_zflag[tile]) != t) __nanosleep(64);
        }
        __syncthreads();
#pragma unroll
        for (int mi = 0; mi < 2; mi++)
#pragma unroll
            for (int ni = 0; ni < 8; ni++) {
                int r = wm + mi * 16 + (lane >> 2);
                int c = wn + ni * 8 + (lane & 3) * 2;
                float2 p0 = *(const float2*)(zp + r * 128 + c);
                float2 p1 = *(const float2*)(zp + (r + 8) * 128 + c);
                acc[mi][ni][0] += p0.x; acc[mi][ni][1] += p0.y;
                acc[mi][ni][2] += p1.x; acc[mi][ni][3] += p1.y;
            }
    }

    // -------- epilogue: smem patch -> gates -> c,h (coalesced, MUFU-light) --------
    __syncthreads();                       // everyone done with stage smem
    float* patch = (float*)smem;           // [128][136] floats
#pragma unroll
    for (int mi = 0; mi < 2; mi++)
#pragma unroll
        for (int ni = 0; ni < 8; ni++) {
            int r = wm + mi * 16 + (lane >> 2);
            int c = wn + ni * 8 + (lane & 3) * 2;
            *(float2*)(patch + r * B_PITCH + c)       = make_float2(acc[mi][ni][0], acc[mi][ni][1]);
            *(float2*)(patch + (r + 8) * B_PITCH + c) = make_float2(acc[mi][ni][2], acc[mi][ni][3]);
        }
    __syncthreads();

    const int jbase = nblk >> 2;           // 32 hidden units per CTA n-tile
#pragma unroll 4
    for (int it = 0; it < 16; it++) {
        int idx = it * 256 + tid;
        int row = idx >> 5;
        int u = idx & 31;
        float4 z = *(float4*)(patch + row * B_PITCH + u * 4);
        float4 bb = *(const float4*)(biasp + ((jbase + u) << 2));
        float ig = sigm_t(z.x + bb.x);
        float fg = sigm_t(z.y + bb.y);
        float gg = tanh_ap(z.z + bb.z);
        float og = sigm_t(z.w + bb.w);
        size_t off = (size_t)(mblk + row) * 1024 + jbase + u;
        float cn = fg * cst[off] + ig * gg;
        cst[off] = cn;
        hout[off] = __float2half(og * tanh_ap(cn));
    }
}

// ---------------- paired, balanced LSTM step ----------------
// bids 0-127:   heavy layer1 tile, chunks [PC,32) + combine  (~24u)
// bids 128-255: light layer0 tile (17u) then heavy partial chunks [0,PC) (~8u)
// PC=8 when light work exists (balanced 25/24); PC=16 on the final heavy-only step.
__global__ __launch_bounds__(256, 2) void lstm_pair(int t0, int t1) {
    extern __shared__ __align__(16) char smem[];
    const int bid = blockIdx.x;
    const int PC = (t0 <= 127) ? 8 : 16;
    if (bid < 128) {
        if (t1 < 0) return;
        gemm_tile(1, t1, bid, PC, 32, 2, smem);          // main heavy + combine
    } else {
        const int tile = bid - 128;
        if (t0 <= 127) gemm_tile(0, t0, tile, 0, 17, 0, smem);   // light tile
        if (t1 >= 0)   gemm_tile(1, t1, tile, 0, PC, 1, smem);   // heavy partial
    }
}

// ---------------- dense sigmoid head ----------------
__global__ void head_kernel(const float* __restrict__ Wd, const float* __restrict__ bd,
                            float* __restrict__ out) {
    int b = blockIdx.x;
    const __half* h = g_h2[1] + (size_t)b * 1024;   // t=127 -> cur buffer = 1
    float s = 0.f;
    for (int j = threadIdx.x; j < 1024; j += 128)
        s += __half2float(h[j]) * Wd[j];
#pragma unroll
    for (int o = 16; o; o >>= 1) s += __shfl_xor_sync(0xffffffffu, s, o);
    __shared__ float ws[4];
    if ((threadIdx.x & 31) == 0) ws[threadIdx.x >> 5] = s;
    __syncthreads();
    if (threadIdx.x == 0) {
        float t = ws[0] + ws[1] + ws[2] + ws[3] + bd[0];
        out[b] = 1.f / (1.f + __expf(-t));
    }
}

// ---------------- launch ----------------
extern "C" void kernel_launch(void* const* d_in, const int* in_sizes, int n_in,
                              void* d_out, int out_size) {
    (void)in_sizes; (void)n_in; (void)out_size;
    const float* x  = (const float*)d_in[0];
    const float* W1 = (const float*)d_in[1];
    const float* U1 = (const float*)d_in[2];
    const float* b1 = (const float*)d_in[3];
    const float* W2 = (const float*)d_in[4];
    const float* U2 = (const float*)d_in[5];
    const float* b2 = (const float*)d_in[6];
    const float* Wd = (const float*)d_in[7];
    const float* bd = (const float*)d_in[8];
    float* out = (float*)d_out;

    cudaFuncSetAttribute(lstm_pair, cudaFuncAttributeMaxDynamicSharedMemorySize, SMEM_TOTAL);

    pack_u1<<<(1088 * 1024 + 255) / 256, 256>>>(W1, U1);       // 1
    pack_u2<<<(2048 * 1024 + 255) / 256, 256>>>(W2, U2);       // 2
    prep_misc<<<(BB * TT * 64 + 255) / 256, 256>>>(x, b1, b2); // 3

    // wavefront: layer0@t0 (light, bids 128-255) + layer1@t0-1 (heavy split-K)
    for (int t0 = 0; t0 <= 128; t0++) {                        // 4 = first lstm (ncu slot)
        lstm_pair<<<256, 256, SMEM_TOTAL>>>(t0, t0 - 1);
    }
    head_kernel<<<512, 128>>>(Wd, bd, out);
}

// round 15
// speedup vs baseline: 1.2750x; 1.1905x over previous
#include <cuda_runtime.h>
#include <cuda_fp16.h>
#include <cstdint>
#include <cstddef>

// Problem constants
#define BB 512
#define TT 128
#define HH 1024
#define BH (512*1024)

// ---------------- device scratch (no allocations allowed) ----------------
__device__ __align__(16) __half g_U1[1088 * 4096];  // [k][n] row-major, gate-interleaved n
__device__ __align__(16) __half g_U2[2048 * 4096];
__device__ __align__(16) float  g_bp1[4096];
__device__ __align__(16) float  g_bp2[4096];
__device__ __align__(16) __half g_xh[BB * TT * 64];
__device__ __align__(16) __half g_h1[2][BH];
__device__ __align__(16) __half g_h2[2][BH];
__device__ __align__(16) float  g_c1[BH];
__device__ __align__(16) float  g_c2[BH];
__device__ __align__(16) float  g_zp[128 * 16384];  // split-K partials (8MB)
__device__ int g_zflag[128];                        // monotonic step tokens (init -1)

// ---------------- ptx helpers ----------------
__device__ __forceinline__ void cp16(uint32_t dst, const void* src) {
    asm volatile("cp.async.cg.shared.global [%0], [%1], 16;\n" :: "r"(dst), "l"(src));
}
__device__ __forceinline__ void cp_commit() { asm volatile("cp.async.commit_group;\n"); }
template<int N> __device__ __forceinline__ void cp_wait() {
    asm volatile("cp.async.wait_group %0;\n" :: "n"(N));
}
__device__ __forceinline__ void ldmA(uint32_t* r, uint32_t a) {
    asm volatile("ldmatrix.sync.aligned.m8n8.x4.shared.b16 {%0,%1,%2,%3}, [%4];\n"
        : "=r"(r[0]), "=r"(r[1]), "=r"(r[2]), "=r"(r[3]) : "r"(a));
}
__device__ __forceinline__ void ldmBT(uint32_t* r, uint32_t a) {
    asm volatile("ldmatrix.sync.aligned.m8n8.x4.trans.shared.b16 {%0,%1,%2,%3}, [%4];\n"
        : "=r"(r[0]), "=r"(r[1]), "=r"(r[2]), "=r"(r[3]) : "r"(a));
}
__device__ __forceinline__ void mma_f16(float c[4], const uint32_t a[4], uint32_t b0, uint32_t b1) {
    asm volatile("mma.sync.aligned.m16n8k16.row.col.f32.f16.f16.f32 "
        "{%0,%1,%2,%3}, {%4,%5,%6,%7}, {%8,%9}, {%0,%1,%2,%3};\n"
        : "+f"(c[0]), "+f"(c[1]), "+f"(c[2]), "+f"(c[3])
        : "r"(a[0]), "r"(a[1]), "r"(a[2]), "r"(a[3]), "r"(b0), "r"(b1));
}
__device__ __forceinline__ float tanh_ap(float x) {
    float y; asm("tanh.approx.f32 %0, %1;" : "=f"(y) : "f"(x)); return y;
}
__device__ __forceinline__ float sigm_t(float x) {   // sigmoid via 1 MUFU
    return fmaf(tanh_ap(0.5f * x), 0.5f, 0.5f);
}
__device__ __forceinline__ int ld_acq(const int* p) {
    int v;
    asm volatile("ld.global.acquire.gpu.b32 %0, [%1];" : "=r"(v) : "l"(p) : "memory");
    return v;
}

// ---------------- pack / prep kernels (run each replay; coalesced) ----------------
__global__ void pack_u1(const float* __restrict__ W1, const float* __restrict__ U1) {
    int idx = blockIdx.x * 256 + threadIdx.x;      // 1088*1024 threads
    if (idx >= 1088 * 1024) return;
    int j = idx & 1023, k = idx >> 10;
    const float* src = (k < 64) ? (W1 + (size_t)k * 4096)
                                : (U1 + (size_t)(k - 64) * 4096);
    union { __half h[4]; uint2 u; } o;
    o.h[0] = __float2half(src[j]);
    o.h[1] = __float2half(src[1024 + j]);
    o.h[2] = __float2half(src[2048 + j]);
    o.h[3] = __float2half(src[3072 + j]);
    *(uint2*)(g_U1 + (size_t)k * 4096 + 4 * j) = o.u;
}
__global__ void pack_u2(const float* __restrict__ W2, const float* __restrict__ U2) {
    int idx = blockIdx.x * 256 + threadIdx.x;      // 2048*1024 threads
    if (idx >= 2048 * 1024) return;
    int j = idx & 1023, k = idx >> 10;
    const float* src = (k < 1024) ? (W2 + (size_t)k * 4096)
                                  : (U2 + (size_t)(k - 1024) * 4096);
    union { __half h[4]; uint2 u; } o;
    o.h[0] = __float2half(src[j]);
    o.h[1] = __float2half(src[1024 + j]);
    o.h[2] = __float2half(src[2048 + j]);
    o.h[3] = __float2half(src[3072 + j]);
    *(uint2*)(g_U2 + (size_t)k * 4096 + 4 * j) = o.u;
}
__global__ void prep_misc(const float* __restrict__ x,
                          const float* __restrict__ b1, const float* __restrict__ b2) {
    int i = blockIdx.x * 256 + threadIdx.x;
    if (i < BB * TT * 64) g_xh[i] = __float2half(x[i]);
    if (i < BH) {
        g_c1[i] = 0.f; g_c2[i] = 0.f;
        __half z = __float2half(0.f);
        g_h1[0][i] = z; g_h1[1][i] = z; g_h2[0][i] = z; g_h2[1][i] = z;
    }
    if (i < 4096) {
        int j = i >> 2, g = i & 3;
        g_bp1[i] = b1[g * 1024 + j];
        g_bp2[i] = b2[g * 1024 + j];
    }
    if (i < 128) g_zflag[i] = -1;
}

// ---------------- cross-SM balanced paired LSTM step ----------------
// Grid 296 = exactly 2 CTAs/SM via LUT_classic[bid % 148] (bid and bid+148 share an SM).
//   bids   0..127 : heavy layer1 main, chunks [0,28), combine + epilogue   (28u)
//   bids 148..275 : light layer0 tile, chunks [0,17), epilogue             (17u)
//   bids 128..147 & 276..295 : collectors on the 20 spare SMs — 3-4 heavy
//                   pieces (chunks [28,32)) each, partial store + flag
// Per-SM sums: H-SMs 45u (was 49), L-SMs ~38u. Single inlined body (I$-safe),
// #pragma unroll 1 work-list loop, no device-function ABI.
#define A_PITCH 72              // halves (64 + 8 pad)
#define B_PITCH 136             // halves (128 + 8 pad)
#define STAGE_A (128 * A_PITCH * 2)     // 18432
#define STAGE_B (64 * B_PITCH * 2)      // 17408
#define STAGE   (STAGE_A + STAGE_B)     // 35840
#define SMEM_TOTAL (3 * STAGE)          // 107520

__global__ __launch_bounds__(256, 2) void lstm_pair(int t0, int t1) {
    extern __shared__ __align__(16) char smem[];
    const int bid = blockIdx.x;
    const int tid = threadIdx.x;
    const int wid = tid >> 5, lane = tid & 31;
    const uint32_t sSm = (uint32_t)__cvta_generic_to_shared(smem);
    const int wm = (wid >> 1) * 32;     // 4 m-warps x 32 rows
    const int wn = (wid & 1) * 64;     // 2 n-warps x 64 cols
    const uint32_t aLane = (uint32_t)(((wm + (lane & 15)) * A_PITCH + ((lane >> 4) << 3)) * 2);
    const uint32_t bLane = (uint32_t)(((lane & 15) * B_PITCH + wn + ((lane >> 4) << 3)) * 2);

    // ---- static work list decoded from bid ----
    int n_items = 0;
    int wl_tile[4], wl_kbeg[4], wl_kend[4], wl_mode[4], wl_layer[4];
    if (bid < 128) {
        if (t1 >= 0) {
            wl_layer[0] = 1; wl_tile[0] = bid; wl_kbeg[0] = 0; wl_kend[0] = 28;
            wl_mode[0] = 2; n_items = 1;                       // heavy main + combine
        }
    } else if (bid >= 148 && bid < 276) {
        if (t0 <= 127) {
            wl_layer[0] = 0; wl_tile[0] = bid - 148; wl_kbeg[0] = 0; wl_kend[0] = 17;
            wl_mode[0] = 0; n_items = 1;                       // light tile
        }
    } else {
        if (t1 >= 0) {
            const int c = (bid < 148) ? (bid - 128) : (bid - 256);   // collector 0..39
            for (int p = c; p < 128; p += 40) {
                wl_layer[n_items] = 1; wl_tile[n_items] = p;
                wl_kbeg[n_items] = 28; wl_kend[n_items] = 32;
                wl_mode[n_items] = 1; n_items++;               // heavy tail piece
            }
        }
    }

#pragma unroll 1
    for (int it = 0; it < n_items; it++) {
        const int layer = wl_layer[it];
        const int tile  = wl_tile[it];
        const int kbeg  = wl_kbeg[it];
        const int kend  = wl_kend[it];
        const int mode  = wl_mode[it];
        const int t = layer ? t1 : t0;

        const int mblk = (tile >> 5) << 7;
        const int nblk = (tile & 31) << 7;
        const int cur = t & 1, prev = cur ^ 1;
        const __half *A0, *A1, *Bw; const float* biasp; float* cst; __half* hout;
        int lda0, K0;
        if (layer == 0) {
            A0 = g_xh + t * 64; lda0 = TT * 64; K0 = 64;
            A1 = g_h1[prev]; Bw = g_U1; biasp = g_bp1; cst = g_c1; hout = g_h1[cur];
        } else {
            A0 = g_h1[cur]; lda0 = 1024; K0 = 1024;
            A1 = g_h2[prev]; Bw = g_U2; biasp = g_bp2; cst = g_c2; hout = g_h2[cur];
        }

        __syncthreads();                 // smem safe vs previous item of this CTA

        float acc[2][8][4];
#pragma unroll
        for (int a = 0; a < 2; a++)
#pragma unroll
            for (int b = 0; b < 8; b++)
#pragma unroll
                for (int c = 0; c < 4; c++) acc[a][b][c] = 0.f;

        auto issue = [&](int kt) {
            const int st = kt % 3;
            const int kg = kt << 6;
            const __half* srcA; int lda, kr;
            if (kg < K0) { srcA = A0; lda = lda0; kr = kg; }
            else         { srcA = A1; lda = 1024; kr = kg - K0; }
            const uint32_t aBase = sSm + st * STAGE;
#pragma unroll
            for (int jj = 0; jj < 4; jj++) {
                int item = jj * 256 + tid;
                int row = item >> 3, c8 = item & 7;
                cp16(aBase + (uint32_t)(row * (A_PITCH * 2) + c8 * 16),
                     srcA + (size_t)(mblk + row) * lda + kr + c8 * 8);
            }
            const uint32_t bBase = aBase + STAGE_A;
#pragma unroll
            for (int jj = 0; jj < 4; jj++) {
                int item = jj * 256 + tid;
                int row = item >> 4, c16 = item & 15;
                cp16(bBase + (uint32_t)(row * (B_PITCH * 2) + c16 * 16),
                     Bw + (size_t)(kg + row) * 4096 + nblk + c16 * 8);
            }
            cp_commit();
        };

        uint32_t af[2][2][4], bf[2][4][4];
        auto load_frags = [&](uint32_t aB, uint32_t bB, int kk, int buf) {
#pragma unroll
            for (int mi = 0; mi < 2; mi++)
                ldmA(af[buf][mi], aB + aLane + (uint32_t)((mi * 16 * A_PITCH + kk * 16) * 2));
#pragma unroll
            for (int nj = 0; nj < 4; nj++)
                ldmBT(bf[buf][nj], bB + bLane + (uint32_t)((kk * 16 * B_PITCH + nj * 16) * 2));
        };
        auto do_mma = [&](int buf) {
#pragma unroll
            for (int mi = 0; mi < 2; mi++)
#pragma unroll
                for (int ni = 0; ni < 8; ni++)
                    mma_f16(acc[mi][ni], af[buf][mi],
                            bf[buf][ni >> 1][(ni & 1) * 2], bf[buf][ni >> 1][(ni & 1) * 2 + 1]);
        };

        // prologue: fill 2 stages; publish first; preload kk0 frags; fill 3rd
        issue(kbeg); issue(kbeg + 1);
        cp_wait<1>();
        __syncthreads();
        {
            const uint32_t aB0 = sSm + (kbeg % 3) * STAGE;
            load_frags(aB0, aB0 + STAGE_A, 0, 0);
        }
        issue(kbeg + 2);

        for (int kt = kbeg; kt < kend; kt++) {
            const uint32_t aB = sSm + (kt % 3) * STAGE;
            const uint32_t bB = aB + STAGE_A;
#pragma unroll
            for (int kk = 0; kk < 3; kk++) {
                load_frags(aB, bB, kk + 1, (kk & 1) ^ 1);
                do_mma(kk & 1);
            }
            if (kt + 2 < kend) cp_wait<1>(); else cp_wait<0>();
            __syncthreads();
            if (kt + 1 < kend) {
                const uint32_t aB2 = sSm + ((kt + 1) % 3) * STAGE;
                load_frags(aB2, aB2 + STAGE_A, 0, 0);
            }
            if (kt + 3 < kend) issue(kt + 3);
            do_mma(1);
        }

        if (mode == 1) {
            // ---- collector: publish partial z + release flag ----
            float* zp = g_zp + (size_t)tile * 16384;
#pragma unroll
            for (int mi = 0; mi < 2; mi++)
#pragma unroll
                for (int ni = 0; ni < 8; ni++) {
                    int r = wm + mi * 16 + (lane >> 2);
                    int c = wn + ni * 8 + (lane & 3) * 2;
                    *(float2*)(zp + r * 128 + c)       = make_float2(acc[mi][ni][0], acc[mi][ni][1]);
                    *(float2*)(zp + (r + 8) * 128 + c) = make_float2(acc[mi][ni][2], acc[mi][ni][3]);
                }
            __threadfence();
            __syncthreads();
            if (tid == 0) atomicExch(&g_zflag[tile], t);
            continue;
        }

        if (mode == 2) {
            // ---- main: wait for the tail partial, fold it in ----
            const float* zp = g_zp + (size_t)tile * 16384;
            if (tid == 0) {
                while (ld_acq(&g_zflag[tile]) != t) __nanosleep(64);
            }
            __syncthreads();
#pragma unroll
            for (int mi = 0; mi < 2; mi++)
#pragma unroll
                for (int ni = 0; ni < 8; ni++) {
                    int r = wm + mi * 16 + (lane >> 2);
                    int c = wn + ni * 8 + (lane & 3) * 2;
                    float2 p0 = *(const float2*)(zp + r * 128 + c);
                    float2 p1 = *(const float2*)(zp + (r + 8) * 128 + c);
                    acc[mi][ni][0] += p0.x; acc[mi][ni][1] += p0.y;
                    acc[mi][ni][2] += p1.x; acc[mi][ni][3] += p1.y;
                }
        }

        // ---- epilogue: smem patch -> gates -> c,h (coalesced, MUFU-light) ----
        __syncthreads();
        float* patch = (float*)smem;
#pragma unroll
        for (int mi = 0; mi < 2; mi++)
#pragma unroll
            for (int ni = 0; ni < 8; ni++) {
                int r = wm + mi * 16 + (lane >> 2);
                int c = wn + ni * 8 + (lane & 3) * 2;
                *(float2*)(patch + r * B_PITCH + c)       = make_float2(acc[mi][ni][0], acc[mi][ni][1]);
                *(float2*)(patch + (r + 8) * B_PITCH + c) = make_float2(acc[mi][ni][2], acc[mi][ni][3]);
            }
        __syncthreads();

        const int jbase = nblk >> 2;
#pragma unroll 4
        for (int it2 = 0; it2 < 16; it2++) {
            int idx = it2 * 256 + tid;
            int row = idx >> 5;
            int u = idx & 31;
            float4 z = *(float4*)(patch + row * B_PITCH + u * 4);
            float4 bb = *(const float4*)(biasp + ((jbase + u) << 2));
            float ig = sigm_t(z.x + bb.x);
            float fg = sigm_t(z.y + bb.y);
            float gg = tanh_ap(z.z + bb.z);
            float og = sigm_t(z.w + bb.w);
            size_t off = (size_t)(mblk + row) * 1024 + jbase + u;
            float cn = fg * cst[off] + ig * gg;
            cst[off] = cn;
            hout[off] = __float2half(og * tanh_ap(cn));
        }
    }
}

// ---------------- dense sigmoid head ----------------
__global__ void head_kernel(const float* __restrict__ Wd, const float* __restrict__ bd,
                            float* __restrict__ out) {
    int b = blockIdx.x;
    const __half* h = g_h2[1] + (size_t)b * 1024;   // t=127 -> cur buffer = 1
    float s = 0.f;
    for (int j = threadIdx.x; j < 1024; j += 128)
        s += __half2float(h[j]) * Wd[j];
#pragma unroll
    for (int o = 16; o; o >>= 1) s += __shfl_xor_sync(0xffffffffu, s, o);
    __shared__ float ws[4];
    if ((threadIdx.x & 31) == 0) ws[threadIdx.x >> 5] = s;
    __syncthreads();
    if (threadIdx.x == 0) {
        float t = ws[0] + ws[1] + ws[2] + ws[3] + bd[0];
        out[b] = 1.f / (1.f + __expf(-t));
    }
}

// ---------------- launch ----------------
extern "C" void kernel_launch(void* const* d_in, const int* in_sizes, int n_in,
                              void* d_out, int out_size) {
    (void)in_sizes; (void)n_in; (void)out_size;
    const float* x  = (const float*)d_in[0];
    const float* W1 = (const float*)d_in[1];
    const float* U1 = (const float*)d_in[2];
    const float* b1 = (const float*)d_in[3];
    const float* W2 = (const float*)d_in[4];
    const float* U2 = (const float*)d_in[5];
    const float* b2 = (const float*)d_in[6];
    const float* Wd = (const float*)d_in[7];
    const float* bd = (const float*)d_in[8];
    float* out = (float*)d_out;

    cudaFuncSetAttribute(lstm_pair, cudaFuncAttributeMaxDynamicSharedMemorySize, SMEM_TOTAL);

    pack_u1<<<(1088 * 1024 + 255) / 256, 256>>>(W1, U1);       // 1
    pack_u2<<<(2048 * 1024 + 255) / 256, 256>>>(W2, U2);       // 2
    prep_misc<<<(BB * TT * 64 + 255) / 256, 256>>>(x, b1, b2); // 3

    // wavefront: light layer0@t0 + heavy layer1@t0-1 with cross-SM K-tail shedding
    for (int t0 = 0; t0 <= 128; t0++) {                        // 4 = first lstm (ncu slot)
        lstm_pair<<<296, 256, SMEM_TOTAL>>>(t0, t0 - 1);
    }
    head_kernel<<<512, 128>>>(Wd, bd, out);
}